// round 9
// baseline (speedup 1.0000x reference)
#include <cuda_runtime.h>
#include <cuda_fp16.h>
#include <mma.h>
#include <math.h>
#include <cstdint>

using namespace nvcuda;

#define N 1024
#define E 128
#define NEG 0.2f

#define I_PER_CTA 8
#define BMJ 64                    // j-rows per CTA
#define LDA_H 136                 // half elements per padded row (272 B)
#define LDCH 136                  // half C stride
// smem byte offsets
#define OFF_A0 0
#define OFF_A1 17408
#define OFF_B  34816
#define OFF_C0 69632
#define OFF_C1 87040
#define OFF_W  104448
#define SMEM_DYN (OFF_W + 512 + 64)

// ---- scratch ----
__device__ float g_base[N * E];
__device__ float g_s[N];
__device__ float g_wa2[E];
__device__ float g_logits[(size_t)N * N];
__device__ __half g_Bh[E * E];   // pc_Wp in fp16, [k][n] row-major

__device__ __forceinline__ float lrelu(float x) { return fmaxf(x, NEG * x); }

// ---------------- fused precompute: wf -> base + s ----------------
__global__ void k_pre(const float* __restrict__ embs, const float* __restrict__ W,
                      const float* __restrict__ pcW, const float* __restrict__ pcb,
                      const float* __restrict__ aW) {
    __shared__ float es[E];
    __shared__ float ws[E];
    __shared__ float red[E];
    int i = blockIdx.x, l = threadIdx.x;
    es[l] = embs[i * E + l];
    __syncthreads();
    float acc = 0.f;
#pragma unroll 8
    for (int k = 0; k < E; k++) acc = fmaf(es[k], W[k * E + l], acc);
    ws[l] = acc;
    red[l] = acc * aW[l];
    __syncthreads();
    float b = pcb[l];
#pragma unroll 8
    for (int k = 0; k < E; k++) b = fmaf(ws[k], pcW[k * E + l], b);
    g_base[i * E + l] = b;
    for (int off = 64; off > 0; off >>= 1) {
        __syncthreads();
        if (l < off) red[l] += red[l + off];
    }
    __syncthreads();
    if (l == 0) g_s[i] = red[0];
}

__global__ void k_wa2(const float* __restrict__ W, const float* __restrict__ aW) {
    __shared__ float a2s[E];
    int m = threadIdx.x;
    a2s[m] = aW[E + m];
    __syncthreads();
    float acc = 0.f;
#pragma unroll 8
    for (int k = 0; k < E; k++) acc = fmaf(W[m * E + k], a2s[k], acc);
    g_wa2[m] = acc;
}

// g_Bh[k][n] = fp16(pc_Wp[k][n])
__global__ void k_bh(const float* __restrict__ pcW) {
    int idx = blockIdx.x * 128 + threadIdx.x;
    g_Bh[idx] = __float2half(pcW[E * E + idx]);
}

// ---------------- fp16 wmma big kernel (fp16 accumulate, 2 k64 chunks) ----------------
// grid (16, 128): blockIdx.x = 64-row j-block, blockIdx.y = i-chunk (8 i's).
__global__ void __launch_bounds__(256, 2)
k_big(const float* __restrict__ pde, const int* __restrict__ adj,
      const float* __restrict__ ab_ptr) {
    extern __shared__ char sm[];
    __half* Ab[2] = { (__half*)(sm + OFF_A0), (__half*)(sm + OFF_A1) };
    __half* Bb = (__half*)(sm + OFF_B);
    __half* Ch[2] = { (__half*)(sm + OFF_C0), (__half*)(sm + OFF_C1) };
    float* wa2s = (float*)(sm + OFF_W);

    const int tid = threadIdx.x;
    const int wid = tid >> 5;
    const int j0 = blockIdx.x * BMJ;
    const int i_base = blockIdx.y * I_PER_CTA;
    const float ab = ab_ptr[0];

    // ---- prologue: B (fp16 copy) + A0 (fp32->fp16) + wa2 ----
#pragma unroll
    for (int t = 0; t < 8; t++) {
        int idx = tid + t * 256;               // 2048 chunks of 8 halves
        int row = idx >> 4, c8 = (idx & 15) * 8;
        *(uint4*)(Bb + row * LDA_H + c8) = *(const uint4*)(g_Bh + row * E + c8);
    }
    {
        const float* gA = pde + ((size_t)i_base * N + j0) * E;
#pragma unroll
        for (int t = 0; t < 4; t++) {
            int idx = tid + t * 256;           // 1024 chunks of 8 floats
            int row = idx >> 4, c8 = (idx & 15) * 8;
            const float4* g = (const float4*)(gA + (size_t)row * E + c8);
            float4 v0 = g[0], v1 = g[1];
            __half2 p0 = __floats2half2_rn(v0.x, v0.y);
            __half2 p1 = __floats2half2_rn(v0.z, v0.w);
            __half2 p2 = __floats2half2_rn(v1.x, v1.y);
            __half2 p3 = __floats2half2_rn(v1.z, v1.w);
            uint4 o;
            o.x = *(uint32_t*)&p0; o.y = *(uint32_t*)&p1;
            o.z = *(uint32_t*)&p2; o.w = *(uint32_t*)&p3;
            *(uint4*)(Ab[0] + row * LDA_H + c8) = o;
        }
    }
    if (tid < E) wa2s[tid] = g_wa2[tid];
    __syncthreads();

    const int wr = (wid & 1) * 32;    // warp row base (0/32)
    const int wc = (wid >> 1) * 32;   // warp col base (0..96)

    for (int s = 0; s < I_PER_CTA; s++) {
        __half* A = Ab[s & 1];

        // 1) issue LDG for next A tile into regs
        float4 stage[8];
        if (s + 1 < I_PER_CTA) {
            const float* gA = pde + ((size_t)(i_base + s + 1) * N + j0) * E;
#pragma unroll
            for (int t = 0; t < 4; t++) {
                int idx = tid + t * 256;
                int row = idx >> 4, c8 = (idx & 15) * 8;
                const float4* g = (const float4*)(gA + (size_t)row * E + c8);
                stage[2 * t] = g[0];
                stage[2 * t + 1] = g[1];
            }
        }

        // 2) epilogue for tile s-1 (C chunks in Ch[], synced at end of prev iter)
        if (s > 0) {
            const int i = i_base + s - 1;
            const int row = tid >> 2, q = tid & 3;
            const __half2* cr0 = (const __half2*)(Ch[0] + row * LDCH) + q * 16;
            const __half2* cr1 = (const __half2*)(Ch[1] + row * LDCH) + q * 16;
            const float* br = g_base + (size_t)(j0 + row) * E + q * 32;
            const float* w2 = wa2s + q * 32;
            float part = 0.f;
#pragma unroll
            for (int u = 0; u < 16; u++) {
                float2 a = __half22float2(cr0[u]);
                float2 b = __half22float2(cr1[u]);
                float2 bv = *(const float2*)(br + 2 * u);
                part = fmaf(lrelu(a.x + b.x + bv.x), w2[2 * u], part);
                part = fmaf(lrelu(a.y + b.y + bv.y), w2[2 * u + 1], part);
            }
            part += __shfl_xor_sync(0xffffffffu, part, 1);
            part += __shfl_xor_sync(0xffffffffu, part, 2);
            if (q == 0) {
                float lg = lrelu(g_s[i] + part + ab);
                size_t oidx = (size_t)i * N + j0 + row;
                g_logits[oidx] = (adj[oidx] == 1) ? lg : -1e30f;
            }
        }

        // 3) fp16 wmma, fp16 accumulate: 64x128x128 as two k64 chunks
        wmma::fragment<wmma::accumulator, 16, 16, 16, __half> fch[2][2][2];
#pragma unroll
        for (int ck = 0; ck < 2; ck++)
#pragma unroll
            for (int r = 0; r < 2; r++)
#pragma unroll
                for (int c = 0; c < 2; c++)
                    wmma::fill_fragment(fch[ck][r][c], __float2half(0.f));

#pragma unroll
        for (int ks = 0; ks < 8; ks++) {
            const int ck = ks >> 2;
            const int k0 = ks * 16;
            wmma::fragment<wmma::matrix_a, 16, 16, 16, __half, wmma::row_major> fa[2];
            wmma::fragment<wmma::matrix_b, 16, 16, 16, __half, wmma::row_major> fb[2];
#pragma unroll
            for (int r = 0; r < 2; r++)
                wmma::load_matrix_sync(fa[r], A + (wr + r * 16) * LDA_H + k0, LDA_H);
#pragma unroll
            for (int c = 0; c < 2; c++)
                wmma::load_matrix_sync(fb[c], Bb + k0 * LDA_H + wc + c * 16, LDA_H);
#pragma unroll
            for (int r = 0; r < 2; r++)
#pragma unroll
                for (int c = 0; c < 2; c++)
                    wmma::mma_sync(fch[ck][r][c], fa[r], fb[c], fch[ck][r][c]);
        }

        // 4) all threads past epilogue reads of Ch and A reads
        __syncthreads();

        // 5) store C chunks; STS staged A[s+1]
#pragma unroll
        for (int ck = 0; ck < 2; ck++)
#pragma unroll
            for (int r = 0; r < 2; r++)
#pragma unroll
                for (int c = 0; c < 2; c++)
                    wmma::store_matrix_sync(Ch[ck] + (wr + r * 16) * LDCH + wc + c * 16,
                                            fch[ck][r][c], LDCH, wmma::mem_row_major);
        if (s + 1 < I_PER_CTA) {
            __half* dst = Ab[1 - (s & 1)];
#pragma unroll
            for (int t = 0; t < 4; t++) {
                int idx = tid + t * 256;
                int row = idx >> 4, c8 = (idx & 15) * 8;
                float4 v0 = stage[2 * t], v1 = stage[2 * t + 1];
                __half2 p0 = __floats2half2_rn(v0.x, v0.y);
                __half2 p1 = __floats2half2_rn(v0.z, v0.w);
                __half2 p2 = __floats2half2_rn(v1.x, v1.y);
                __half2 p3 = __floats2half2_rn(v1.z, v1.w);
                uint4 o;
                o.x = *(uint32_t*)&p0; o.y = *(uint32_t*)&p1;
                o.z = *(uint32_t*)&p2; o.w = *(uint32_t*)&p3;
                *(uint4*)(dst + row * LDA_H + c8) = o;
            }
        }
        __syncthreads();
    }

    // final epilogue: tile 7
    {
        const int i = i_base + I_PER_CTA - 1;
        const int row = tid >> 2, q = tid & 3;
        const __half2* cr0 = (const __half2*)(Ch[0] + row * LDCH) + q * 16;
        const __half2* cr1 = (const __half2*)(Ch[1] + row * LDCH) + q * 16;
        const float* br = g_base + (size_t)(j0 + row) * E + q * 32;
        const float* w2 = wa2s + q * 32;
        float part = 0.f;
#pragma unroll
        for (int u = 0; u < 16; u++) {
            float2 a = __half22float2(cr0[u]);
            float2 b = __half22float2(cr1[u]);
            float2 bv = *(const float2*)(br + 2 * u);
            part = fmaf(lrelu(a.x + b.x + bv.x), w2[2 * u], part);
            part = fmaf(lrelu(a.y + b.y + bv.y), w2[2 * u + 1], part);
        }
        part += __shfl_xor_sync(0xffffffffu, part, 1);
        part += __shfl_xor_sync(0xffffffffu, part, 2);
        if (q == 0) {
            float lg = lrelu(g_s[i] + part + ab);
            size_t oidx = (size_t)i * N + j0 + row;
            g_logits[oidx] = (adj[oidx] == 1) ? lg : -1e30f;
        }
    }
}

// ---------------- softmax + attn@embs + concat ----------------
#define RPB 8
__global__ void __launch_bounds__(256)
k_out(const float* __restrict__ embs, float* __restrict__ out) {
    __shared__ float attn[RPB][N];       // 32 KB
    __shared__ float red[256];
    __shared__ float partial[RPB][E];    // 4 KB
    const int i0 = blockIdx.x * RPB;
    const int t = threadIdx.x;

    float inv[RPB];
#pragma unroll
    for (int r = 0; r < RPB; r++) {
        const float* lg = g_logits + (size_t)(i0 + r) * N;
        float m = -1e30f;
#pragma unroll
        for (int q = 0; q < N / 256; q++) m = fmaxf(m, lg[t + q * 256]);
        red[t] = m;
        for (int off = 128; off > 0; off >>= 1) {
            __syncthreads();
            if (t < off) red[t] = fmaxf(red[t], red[t + off]);
        }
        __syncthreads();
        m = red[0];
        __syncthreads();
        float s = 0.f;
#pragma unroll
        for (int q = 0; q < N / 256; q++) {
            float e = expf(lg[t + q * 256] - m);
            attn[r][t + q * 256] = e;
            s += e;
        }
        red[t] = s;
        for (int off = 128; off > 0; off >>= 1) {
            __syncthreads();
            if (t < off) red[t] += red[t + off];
        }
        __syncthreads();
        inv[r] = 1.f / red[0];
        __syncthreads();
    }

    // nbc: split j-range over 2 halves of the block
    const int col = t & 127, h = t >> 7;
    float acc[RPB];
#pragma unroll
    for (int r = 0; r < RPB; r++) acc[r] = 0.f;
    const int jb = h * 512;
#pragma unroll 8
    for (int j = jb; j < jb + 512; j++) {
        float ev = embs[j * E + col];
#pragma unroll
        for (int r = 0; r < RPB; r++) acc[r] = fmaf(attn[r][j], ev, acc[r]);
    }
    if (h == 1) {
#pragma unroll
        for (int r = 0; r < RPB; r++) partial[r][col] = acc[r];
    }
    __syncthreads();
    if (h == 0) {
#pragma unroll
        for (int r = 0; r < RPB; r++) {
            int i = i0 + r;
            out[(size_t)i * (2 * E) + col] = embs[i * E + col];
            out[(size_t)i * (2 * E) + E + col] = (acc[r] + partial[r][col]) * inv[r];
        }
    }
}

// ---------------- launch ----------------
extern "C" void kernel_launch(void* const* d_in, const int* in_sizes, int n_in,
                              void* d_out, int out_size) {
    const float* embs = (const float*)d_in[0];
    const int*   adj  = (const int*)d_in[1];
    const float* pde  = (const float*)d_in[2];
    const float* W    = (const float*)d_in[3];
    const float* pcW  = (const float*)d_in[4];
    const float* pcb  = (const float*)d_in[5];
    const float* aW   = (const float*)d_in[6];
    const float* ab   = (const float*)d_in[7];
    float* out = (float*)d_out;

    cudaFuncSetAttribute(k_big, cudaFuncAttributeMaxDynamicSharedMemorySize,
                         (int)SMEM_DYN);

    k_pre<<<N, E>>>(embs, W, pcW, pcb, aW);                       // launch 0
    k_wa2<<<1, E>>>(W, aW);                                       // launch 1
    k_bh<<<E, E>>>(pcW);                                          // launch 2
    k_big<<<dim3(N / BMJ, N / I_PER_CTA), 256, SMEM_DYN>>>(pde, adj, ab);  // launch 3 (profiled)
    k_out<<<N / RPB, 256>>>(embs, out);                           // launch 4
}

// round 11
// speedup vs baseline: 1.8143x; 1.8143x over previous
#include <cuda_runtime.h>
#include <cuda_fp16.h>
#include <mma.h>
#include <math.h>
#include <cstdint>

using namespace nvcuda;

#define N 1024
#define E 128
#define NEG 0.2f

#define I_PER_CTA 8
#define BMJ 128                   // j-rows per CTA
#define LDH 136                   // half stride (272 B rows)
#define TILE_B (BMJ * LDH * 2)    // 34816 B
// smem byte offsets
#define OFF_A0 0
#define OFF_A1 34816
#define OFF_B  69632
#define OFF_C  104448
#define OFF_BS 139264
#define OFF_W  174080
#define SMEM_DYN (OFF_W + 512)

// ---- scratch ----
__device__ float g_base[N * E];
__device__ float g_s[N];
__device__ float g_wa2[E];
__device__ float g_logits[(size_t)N * N];
__device__ __half g_Bh[E * E];   // pc_Wp fp16, [k][n]

__device__ __forceinline__ float lrelu(float x) { return fmaxf(x, NEG * x); }

// ---------------- precompute ----------------
__global__ void k_pre(const float* __restrict__ embs, const float* __restrict__ W,
                      const float* __restrict__ pcW, const float* __restrict__ pcb,
                      const float* __restrict__ aW) {
    __shared__ float es[E];
    __shared__ float ws[E];
    __shared__ float red[E];
    int i = blockIdx.x, l = threadIdx.x;
    es[l] = embs[i * E + l];
    __syncthreads();
    float acc = 0.f;
#pragma unroll 8
    for (int k = 0; k < E; k++) acc = fmaf(es[k], W[k * E + l], acc);
    ws[l] = acc;
    red[l] = acc * aW[l];
    __syncthreads();
    float b = pcb[l];
#pragma unroll 8
    for (int k = 0; k < E; k++) b = fmaf(ws[k], pcW[k * E + l], b);
    g_base[i * E + l] = b;
    for (int off = 64; off > 0; off >>= 1) {
        __syncthreads();
        if (l < off) red[l] += red[l + off];
    }
    __syncthreads();
    if (l == 0) g_s[i] = red[0];
}

__global__ void k_wa2(const float* __restrict__ W, const float* __restrict__ aW) {
    __shared__ float a2s[E];
    int m = threadIdx.x;
    a2s[m] = aW[E + m];
    __syncthreads();
    float acc = 0.f;
#pragma unroll 8
    for (int k = 0; k < E; k++) acc = fmaf(W[m * E + k], a2s[k], acc);
    g_wa2[m] = acc;
}

__global__ void k_bh(const float* __restrict__ pcW) {
    int idx = blockIdx.x * 128 + threadIdx.x;
    g_Bh[idx] = __float2half(pcW[E * E + idx]);
}

// ---------------- big kernel: 128x128 tiles, warp tile 32x64, fp16 acc ----------------
// grid (8, 128): blockIdx.x = 128-row j-block, blockIdx.y = 8-i chunk.
__global__ void __launch_bounds__(256)
k_big(const float* __restrict__ pde, const int* __restrict__ adj,
      const float* __restrict__ ab_ptr) {
    extern __shared__ char sm[];
    __half* Ab[2] = { (__half*)(sm + OFF_A0), (__half*)(sm + OFF_A1) };
    __half* Bs = (__half*)(sm + OFF_B);
    __half* Cs = (__half*)(sm + OFF_C);
    __half* bs = (__half*)(sm + OFF_BS);
    float* wa2s = (float*)(sm + OFF_W);

    const int tid = threadIdx.x;
    const int wid = tid >> 5;
    const int j0 = blockIdx.x * BMJ;
    const int i_base = blockIdx.y * I_PER_CTA;
    const float ab = ab_ptr[0];

    // ---- prologue: B, base->fp16, A0 (fp32->fp16), wa2 ----
#pragma unroll
    for (int t = 0; t < 8; t++) {
        int idx = tid + t * 256;               // 2048 chunks of 8 halves
        int row = idx >> 4, c8 = (idx & 15) * 8;
        *(uint4*)(Bs + row * LDH + c8) = *(const uint4*)(g_Bh + row * E + c8);
    }
#pragma unroll
    for (int t = 0; t < 8; t++) {
        int idx = tid + t * 256;
        int row = idx >> 4, c8 = (idx & 15) * 8;
        const float4* g = (const float4*)(g_base + (size_t)(j0 + row) * E + c8);
        float4 v0 = g[0], v1 = g[1];
        __half2 p0 = __floats2half2_rn(v0.x, v0.y);
        __half2 p1 = __floats2half2_rn(v0.z, v0.w);
        __half2 p2 = __floats2half2_rn(v1.x, v1.y);
        __half2 p3 = __floats2half2_rn(v1.z, v1.w);
        uint4 o;
        o.x = *(uint32_t*)&p0; o.y = *(uint32_t*)&p1;
        o.z = *(uint32_t*)&p2; o.w = *(uint32_t*)&p3;
        *(uint4*)(bs + row * LDH + c8) = o;
    }
    {
        const float* gA = pde + ((size_t)i_base * N + j0) * E;
#pragma unroll
        for (int t = 0; t < 8; t++) {
            int idx = tid + t * 256;
            int row = idx >> 4, c8 = (idx & 15) * 8;
            const float4* g = (const float4*)(gA + (size_t)row * E + c8);
            float4 v0 = g[0], v1 = g[1];
            __half2 p0 = __floats2half2_rn(v0.x, v0.y);
            __half2 p1 = __floats2half2_rn(v0.z, v0.w);
            __half2 p2 = __floats2half2_rn(v1.x, v1.y);
            __half2 p3 = __floats2half2_rn(v1.z, v1.w);
            uint4 o;
            o.x = *(uint32_t*)&p0; o.y = *(uint32_t*)&p1;
            o.z = *(uint32_t*)&p2; o.w = *(uint32_t*)&p3;
            *(uint4*)(Ab[0] + row * LDH + c8) = o;
        }
    }
    if (tid < E) wa2s[tid] = g_wa2[tid];
    __syncthreads();

    // warp partition: 4 row-groups x 2 col-groups, warp tile 32x64
    const int wr = (wid & 3) * 32;
    const int wc = (wid >> 2) * 64;

    for (int s = 0; s < I_PER_CTA; s++) {
        __half* A = Ab[s & 1];

        // 1) stage next A tile into regs (latency overlaps epilogue+mma)
        float4 stage[16];
        if (s + 1 < I_PER_CTA) {
            const float* gA = pde + ((size_t)(i_base + s + 1) * N + j0) * E;
#pragma unroll
            for (int t = 0; t < 8; t++) {
                int idx = tid + t * 256;
                int row = idx >> 4, c8 = (idx & 15) * 8;
                const float4* g = (const float4*)(gA + (size_t)row * E + c8);
                stage[2 * t] = g[0];
                stage[2 * t + 1] = g[1];
            }
        }

        // 2) epilogue for tile s-1 (C in Cs, protected by end-of-prev-iter sync)
        if (s > 0) {
            const int i = i_base + s - 1;
            const int row = tid >> 1, h = tid & 1;
            const __half2* cr = (const __half2*)(Cs + row * LDH) + h * 32;
            const __half2* br = (const __half2*)(bs + row * LDH) + h * 32;
            const float* w2 = wa2s + h * 64;
            float part = 0.f;
#pragma unroll
            for (int u = 0; u < 32; u++) {
                float2 a = __half22float2(cr[u]);
                float2 b = __half22float2(br[u]);
                part = fmaf(lrelu(a.x + b.x), w2[2 * u], part);
                part = fmaf(lrelu(a.y + b.y), w2[2 * u + 1], part);
            }
            part += __shfl_xor_sync(0xffffffffu, part, 1);
            if (h == 0) {
                float lg = lrelu(g_s[i] + part + ab);
                size_t oidx = (size_t)i * N + j0 + row;
                g_logits[oidx] = (adj[oidx] == 1) ? lg : -1e30f;
            }
        }

        // 3) fp16 wmma (fp16 acc): 128x128x128, warp tile 32x64
        wmma::fragment<wmma::accumulator, 16, 16, 16, __half> fc[2][4];
#pragma unroll
        for (int r = 0; r < 2; r++)
#pragma unroll
            for (int c = 0; c < 4; c++) wmma::fill_fragment(fc[r][c], __float2half(0.f));

#pragma unroll
        for (int ks = 0; ks < 8; ks++) {
            const int k0 = ks * 16;
            wmma::fragment<wmma::matrix_a, 16, 16, 16, __half, wmma::row_major> fa[2];
            wmma::fragment<wmma::matrix_b, 16, 16, 16, __half, wmma::row_major> fb[4];
#pragma unroll
            for (int r = 0; r < 2; r++)
                wmma::load_matrix_sync(fa[r], A + (wr + r * 16) * LDH + k0, LDH);
#pragma unroll
            for (int c = 0; c < 4; c++)
                wmma::load_matrix_sync(fb[c], Bs + k0 * LDH + wc + c * 16, LDH);
#pragma unroll
            for (int r = 0; r < 2; r++)
#pragma unroll
                for (int c = 0; c < 4; c++)
                    wmma::mma_sync(fc[r][c], fa[r], fb[c], fc[r][c]);
        }

        // 4) epilogue reads of Cs done; mma reads of A buffers done
        __syncthreads();

        // 5) store C; STS staged A[s+1]
#pragma unroll
        for (int r = 0; r < 2; r++)
#pragma unroll
            for (int c = 0; c < 4; c++)
                wmma::store_matrix_sync(Cs + (wr + r * 16) * LDH + wc + c * 16,
                                        fc[r][c], LDH, wmma::mem_row_major);
        if (s + 1 < I_PER_CTA) {
            __half* dst = Ab[1 - (s & 1)];
#pragma unroll
            for (int t = 0; t < 8; t++) {
                int idx = tid + t * 256;
                int row = idx >> 4, c8 = (idx & 15) * 8;
                float4 v0 = stage[2 * t], v1 = stage[2 * t + 1];
                __half2 p0 = __floats2half2_rn(v0.x, v0.y);
                __half2 p1 = __floats2half2_rn(v0.z, v0.w);
                __half2 p2 = __floats2half2_rn(v1.x, v1.y);
                __half2 p3 = __floats2half2_rn(v1.z, v1.w);
                uint4 o;
                o.x = *(uint32_t*)&p0; o.y = *(uint32_t*)&p1;
                o.z = *(uint32_t*)&p2; o.w = *(uint32_t*)&p3;
                *(uint4*)(dst + row * LDH + c8) = o;
            }
        }
        __syncthreads();
    }

    // ---- final epilogue: tile 7 ----
    {
        const int i = i_base + I_PER_CTA - 1;
        const int row = tid >> 1, h = tid & 1;
        const __half2* cr = (const __half2*)(Cs + row * LDH) + h * 32;
        const __half2* br = (const __half2*)(bs + row * LDH) + h * 32;
        const float* w2 = wa2s + h * 64;
        float part = 0.f;
#pragma unroll
        for (int u = 0; u < 32; u++) {
            float2 a = __half22float2(cr[u]);
            float2 b = __half22float2(br[u]);
            part = fmaf(lrelu(a.x + b.x), w2[2 * u], part);
            part = fmaf(lrelu(a.y + b.y), w2[2 * u + 1], part);
        }
        part += __shfl_xor_sync(0xffffffffu, part, 1);
        if (h == 0) {
            float lg = lrelu(g_s[i] + part + ab);
            size_t oidx = (size_t)i * N + j0 + row;
            g_logits[oidx] = (adj[oidx] == 1) ? lg : -1e30f;
        }
    }
}

// ---------------- softmax + attn@embs + concat ----------------
#define RPB 8
__global__ void __launch_bounds__(256)
k_out(const float* __restrict__ embs, float* __restrict__ out) {
    __shared__ float attn[RPB][N];
    __shared__ float red[256];
    __shared__ float partial[RPB][E];
    const int i0 = blockIdx.x * RPB;
    const int t = threadIdx.x;

    float inv[RPB];
#pragma unroll
    for (int r = 0; r < RPB; r++) {
        const float* lg = g_logits + (size_t)(i0 + r) * N;
        float m = -1e30f;
#pragma unroll
        for (int q = 0; q < N / 256; q++) m = fmaxf(m, lg[t + q * 256]);
        red[t] = m;
        for (int off = 128; off > 0; off >>= 1) {
            __syncthreads();
            if (t < off) red[t] = fmaxf(red[t], red[t + off]);
        }
        __syncthreads();
        m = red[0];
        __syncthreads();
        float s = 0.f;
#pragma unroll
        for (int q = 0; q < N / 256; q++) {
            float e = expf(lg[t + q * 256] - m);
            attn[r][t + q * 256] = e;
            s += e;
        }
        red[t] = s;
        for (int off = 128; off > 0; off >>= 1) {
            __syncthreads();
            if (t < off) red[t] += red[t + off];
        }
        __syncthreads();
        inv[r] = 1.f / red[0];
        __syncthreads();
    }

    const int col = t & 127, h = t >> 7;
    float acc[RPB];
#pragma unroll
    for (int r = 0; r < RPB; r++) acc[r] = 0.f;
    const int jb = h * 512;
#pragma unroll 8
    for (int j = jb; j < jb + 512; j++) {
        float ev = embs[j * E + col];
#pragma unroll
        for (int r = 0; r < RPB; r++) acc[r] = fmaf(attn[r][j], ev, acc[r]);
    }
    if (h == 1) {
#pragma unroll
        for (int r = 0; r < RPB; r++) partial[r][col] = acc[r];
    }
    __syncthreads();
    if (h == 0) {
#pragma unroll
        for (int r = 0; r < RPB; r++) {
            int i = i0 + r;
            out[(size_t)i * (2 * E) + col] = embs[i * E + col];
            out[(size_t)i * (2 * E) + E + col] = (acc[r] + partial[r][col]) * inv[r];
        }
    }
}

// ---------------- launch ----------------
extern "C" void kernel_launch(void* const* d_in, const int* in_sizes, int n_in,
                              void* d_out, int out_size) {
    const float* embs = (const float*)d_in[0];
    const int*   adj  = (const int*)d_in[1];
    const float* pde  = (const float*)d_in[2];
    const float* W    = (const float*)d_in[3];
    const float* pcW  = (const float*)d_in[4];
    const float* pcb  = (const float*)d_in[5];
    const float* aW   = (const float*)d_in[6];
    const float* ab   = (const float*)d_in[7];
    float* out = (float*)d_out;

    cudaFuncSetAttribute(k_big, cudaFuncAttributeMaxDynamicSharedMemorySize,
                         (int)SMEM_DYN);

    k_pre<<<N, E>>>(embs, W, pcW, pcb, aW);                       // launch 0
    k_wa2<<<1, E>>>(W, aW);                                       // launch 1
    k_bh<<<E, E>>>(pcW);                                          // launch 2
    k_big<<<dim3(N / BMJ, N / I_PER_CTA), 256, SMEM_DYN>>>(pde, adj, ab);  // launch 3
    k_out<<<N / RPB, 256>>>(embs, out);                           // launch 4
}

// round 12
// speedup vs baseline: 1.9264x; 1.0618x over previous
#include <cuda_runtime.h>
#include <cuda_fp16.h>
#include <mma.h>
#include <math.h>
#include <cstdint>

using namespace nvcuda;

#define N 1024
#define E 128
#define NEG 0.2f

#define I_PER_CTA 8
#define BMJ 128                   // j-rows per CTA
#define LDH 136                   // half stride (272 B rows)
#define TILE_B (BMJ * LDH * 2)    // 34816 B
// smem byte offsets
#define OFF_A0 0
#define OFF_A1 34816
#define OFF_B  69632
#define OFF_C  104448
#define OFF_BS 139264
#define OFF_W2 174080             // [128][16] fp16 = 4096 B
#define OFF_R  178176             // [8 warps][16][16] fp32 = 8192 B
#define SMEM_DYN (OFF_R + 8192)

// ---- scratch ----
__device__ float g_base[N * E];
__device__ float g_s[N];
__device__ float g_wa2[E];
__device__ float g_logits[(size_t)N * N];
__device__ __half g_Bh[E * E];   // pc_Wp fp16, [k][n]

__device__ __forceinline__ float lrelu(float x) { return fmaxf(x, NEG * x); }

// ---------------- precompute ----------------
__global__ void k_pre(const float* __restrict__ embs, const float* __restrict__ W,
                      const float* __restrict__ pcW, const float* __restrict__ pcb,
                      const float* __restrict__ aW) {
    __shared__ float es[E];
    __shared__ float ws[E];
    __shared__ float red[E];
    int i = blockIdx.x, l = threadIdx.x;
    es[l] = embs[i * E + l];
    __syncthreads();
    float acc = 0.f;
#pragma unroll 8
    for (int k = 0; k < E; k++) acc = fmaf(es[k], W[k * E + l], acc);
    ws[l] = acc;
    red[l] = acc * aW[l];
    __syncthreads();
    float b = pcb[l];
#pragma unroll 8
    for (int k = 0; k < E; k++) b = fmaf(ws[k], pcW[k * E + l], b);
    g_base[i * E + l] = b;
    for (int off = 64; off > 0; off >>= 1) {
        __syncthreads();
        if (l < off) red[l] += red[l + off];
    }
    __syncthreads();
    if (l == 0) g_s[i] = red[0];
}

__global__ void k_wa2(const float* __restrict__ W, const float* __restrict__ aW) {
    __shared__ float a2s[E];
    int m = threadIdx.x;
    a2s[m] = aW[E + m];
    __syncthreads();
    float acc = 0.f;
#pragma unroll 8
    for (int k = 0; k < E; k++) acc = fmaf(W[m * E + k], a2s[k], acc);
    g_wa2[m] = acc;
}

__global__ void k_bh(const float* __restrict__ pcW) {
    int idx = blockIdx.x * 128 + threadIdx.x;
    g_Bh[idx] = __float2half(pcW[E * E + idx]);
}

// ---------------- big kernel ----------------
// grid (8, 128): blockIdx.x = 128-row j-block, blockIdx.y = 8-i chunk.
__global__ void __launch_bounds__(256)
k_big(const float* __restrict__ pde, const int* __restrict__ adj,
      const float* __restrict__ ab_ptr) {
    extern __shared__ char sm[];
    __half* Ab[2] = { (__half*)(sm + OFF_A0), (__half*)(sm + OFF_A1) };
    __half* Bs = (__half*)(sm + OFF_B);
    __half* Cs = (__half*)(sm + OFF_C);     // P tile
    __half* bs = (__half*)(sm + OFF_BS);    // base tile fp16
    __half* w2s = (__half*)(sm + OFF_W2);   // [128][16], col0 = wa2
    float* rs = (float*)(sm + OFF_R);

    const int tid = threadIdx.x;
    const int wid = tid >> 5;
    const int lane = tid & 31;
    const int j0 = blockIdx.x * BMJ;
    const int i_base = blockIdx.y * I_PER_CTA;
    const float ab = ab_ptr[0];
    const __half2 slope = __float2half2_rn(NEG);

    // ---- prologue ----
#pragma unroll
    for (int t = 0; t < 8; t++) {
        int idx = tid + t * 256;
        int row = idx >> 4, c8 = (idx & 15) * 8;
        *(uint4*)(Bs + row * LDH + c8) = *(const uint4*)(g_Bh + row * E + c8);
    }
#pragma unroll
    for (int t = 0; t < 8; t++) {
        int idx = tid + t * 256;
        int row = idx >> 4, c8 = (idx & 15) * 8;
        const float4* g = (const float4*)(g_base + (size_t)(j0 + row) * E + c8);
        float4 v0 = g[0], v1 = g[1];
        __half2 p0 = __floats2half2_rn(v0.x, v0.y);
        __half2 p1 = __floats2half2_rn(v0.z, v0.w);
        __half2 p2 = __floats2half2_rn(v1.x, v1.y);
        __half2 p3 = __floats2half2_rn(v1.z, v1.w);
        uint4 o;
        o.x = *(uint32_t*)&p0; o.y = *(uint32_t*)&p1;
        o.z = *(uint32_t*)&p2; o.w = *(uint32_t*)&p3;
        *(uint4*)(bs + row * LDH + c8) = o;
    }
    {
        const float* gA = pde + ((size_t)i_base * N + j0) * E;
#pragma unroll
        for (int t = 0; t < 8; t++) {
            int idx = tid + t * 256;
            int row = idx >> 4, c8 = (idx & 15) * 8;
            const float4* g = (const float4*)(gA + (size_t)row * E + c8);
            float4 v0 = g[0], v1 = g[1];
            __half2 p0 = __floats2half2_rn(v0.x, v0.y);
            __half2 p1 = __floats2half2_rn(v0.z, v0.w);
            __half2 p2 = __floats2half2_rn(v1.x, v1.y);
            __half2 p3 = __floats2half2_rn(v1.z, v1.w);
            uint4 o;
            o.x = *(uint32_t*)&p0; o.y = *(uint32_t*)&p1;
            o.z = *(uint32_t*)&p2; o.w = *(uint32_t*)&p3;
            *(uint4*)(Ab[0] + row * LDH + c8) = o;
        }
    }
    // w2s: [128][16], col 0 = wa2 fp16, rest 0
#pragma unroll
    for (int t = 0; t < 8; t++) {
        int idx = tid + t * 256;   // 2048 halves
        w2s[idx] = ((idx & 15) == 0) ? __float2half(g_wa2[idx >> 4]) : __half(0);
    }
    __syncthreads();

    // warp partition: 4 row-groups x 2 col-groups, warp tile 32x64
    const int wr = (wid & 3) * 32;
    const int wc = (wid >> 2) * 64;

    // base fragments, loaded once (acc layout matches fc)
    wmma::fragment<wmma::accumulator, 16, 16, 16, __half> bfrag[2][4];
#pragma unroll
    for (int r = 0; r < 2; r++)
#pragma unroll
        for (int c = 0; c < 4; c++)
            wmma::load_matrix_sync(bfrag[r][c], bs + (wr + r * 16) * LDH + wc + c * 16,
                                   LDH, wmma::mem_row_major);

    float* rsumw = rs + wid * 256;   // [16][16] fp32, warp-private

    for (int s = 0; s < I_PER_CTA; s++) {
        __half* A = Ab[s & 1];
        const int i = i_base + s;

        // 1) stage next A tile into regs
        float4 stage[16];
        if (s + 1 < I_PER_CTA) {
            const float* gA = pde + ((size_t)(i_base + s + 1) * N + j0) * E;
#pragma unroll
            for (int t = 0; t < 8; t++) {
                int idx = tid + t * 256;
                int row = idx >> 4, c8 = (idx & 15) * 8;
                const float4* g = (const float4*)(gA + (size_t)row * E + c8);
                stage[2 * t] = g[0];
                stage[2 * t + 1] = g[1];
            }
        }

        // 2) main mma: 128x128x128, fp16 acc, warp tile 32x64
        wmma::fragment<wmma::accumulator, 16, 16, 16, __half> fc[2][4];
#pragma unroll
        for (int r = 0; r < 2; r++)
#pragma unroll
            for (int c = 0; c < 4; c++) wmma::fill_fragment(fc[r][c], __float2half(0.f));

#pragma unroll
        for (int ks = 0; ks < 8; ks++) {
            const int k0 = ks * 16;
            wmma::fragment<wmma::matrix_a, 16, 16, 16, __half, wmma::row_major> fa[2];
            wmma::fragment<wmma::matrix_b, 16, 16, 16, __half, wmma::row_major> fb[4];
#pragma unroll
            for (int r = 0; r < 2; r++)
                wmma::load_matrix_sync(fa[r], A + (wr + r * 16) * LDH + k0, LDH);
#pragma unroll
            for (int c = 0; c < 4; c++)
                wmma::load_matrix_sync(fb[c], Bs + k0 * LDH + wc + c * 16, LDH);
#pragma unroll
            for (int r = 0; r < 2; r++)
#pragma unroll
                for (int c = 0; c < 4; c++)
                    wmma::mma_sync(fc[r][c], fa[r], fb[c], fc[r][c]);
        }
        __syncthreads();   // sync1: A-buffer reads done; prev reduction reads of Cs done

        // 3) P = lrelu(fc + base) elementwise; store P; STS staged A
#pragma unroll
        for (int r = 0; r < 2; r++)
#pragma unroll
            for (int c = 0; c < 4; c++) {
                __half2* p = reinterpret_cast<__half2*>(fc[r][c].x);
                const __half2* b2 = reinterpret_cast<const __half2*>(bfrag[r][c].x);
#pragma unroll
                for (int e = 0; e < 4; e++) {
                    __half2 v = __hadd2(p[e], b2[e]);
                    p[e] = __hmax2(v, __hmul2(v, slope));
                }
                wmma::store_matrix_sync(Cs + (wr + r * 16) * LDH + wc + c * 16,
                                        fc[r][c], LDH, wmma::mem_row_major);
            }
        if (s + 1 < I_PER_CTA) {
            __half* dst = Ab[1 - (s & 1)];
#pragma unroll
            for (int t = 0; t < 8; t++) {
                int idx = tid + t * 256;
                int row = idx >> 4, c8 = (idx & 15) * 8;
                float4 v0 = stage[2 * t], v1 = stage[2 * t + 1];
                __half2 p0 = __floats2half2_rn(v0.x, v0.y);
                __half2 p1 = __floats2half2_rn(v0.z, v0.w);
                __half2 p2 = __floats2half2_rn(v1.x, v1.y);
                __half2 p3 = __floats2half2_rn(v1.z, v1.w);
                uint4 o;
                o.x = *(uint32_t*)&p0; o.y = *(uint32_t*)&p1;
                o.z = *(uint32_t*)&p2; o.w = *(uint32_t*)&p3;
                *(uint4*)(dst + row * LDH + c8) = o;
            }
        }
        __syncthreads();   // sync2: P tile fully visible

        // 4) reduction mma: rowsum[16x16] = P[wid*16..+16][0:128] @ w2s[128][16]
        {
            wmma::fragment<wmma::accumulator, 16, 16, 16, float> racc;
            wmma::fill_fragment(racc, 0.f);
#pragma unroll
            for (int ks = 0; ks < 8; ks++) {
                wmma::fragment<wmma::matrix_a, 16, 16, 16, __half, wmma::row_major> pa;
                wmma::fragment<wmma::matrix_b, 16, 16, 16, __half, wmma::row_major> wb;
                wmma::load_matrix_sync(pa, Cs + (wid * 16) * LDH + ks * 16, LDH);
                wmma::load_matrix_sync(wb, w2s + ks * 16 * 16, 16);
                wmma::mma_sync(racc, pa, wb, racc);
            }
            wmma::store_matrix_sync(rsumw, racc, 16, wmma::mem_row_major);
            __syncwarp();
            if (lane < 16) {
                int row = wid * 16 + lane;
                float part = rsumw[lane * 16];   // col 0
                float lg = lrelu(g_s[i] + part + ab);
                size_t oidx = (size_t)i * N + j0 + row;
                g_logits[oidx] = (adj[oidx] == 1) ? lg : -1e30f;
            }
            __syncwarp();
        }
    }
}

// ---------------- softmax + attn@embs + concat ----------------
#define RPB 8
__global__ void __launch_bounds__(256)
k_out(const float* __restrict__ embs, float* __restrict__ out) {
    __shared__ float attn[RPB][N];
    __shared__ float red[256];
    __shared__ float partial[RPB][E];
    const int i0 = blockIdx.x * RPB;
    const int t = threadIdx.x;

    float inv[RPB];
#pragma unroll
    for (int r = 0; r < RPB; r++) {
        const float* lg = g_logits + (size_t)(i0 + r) * N;
        float m = -1e30f;
#pragma unroll
        for (int q = 0; q < N / 256; q++) m = fmaxf(m, lg[t + q * 256]);
        red[t] = m;
        for (int off = 128; off > 0; off >>= 1) {
            __syncthreads();
            if (t < off) red[t] = fmaxf(red[t], red[t + off]);
        }
        __syncthreads();
        m = red[0];
        __syncthreads();
        float s = 0.f;
#pragma unroll
        for (int q = 0; q < N / 256; q++) {
            float e = expf(lg[t + q * 256] - m);
            attn[r][t + q * 256] = e;
            s += e;
        }
        red[t] = s;
        for (int off = 128; off > 0; off >>= 1) {
            __syncthreads();
            if (t < off) red[t] += red[t + off];
        }
        __syncthreads();
        inv[r] = 1.f / red[0];
        __syncthreads();
    }

    const int col = t & 127, h = t >> 7;
    float acc[RPB];
#pragma unroll
    for (int r = 0; r < RPB; r++) acc[r] = 0.f;
    const int jb = h * 512;
#pragma unroll 8
    for (int j = jb; j < jb + 512; j++) {
        float ev = embs[j * E + col];
#pragma unroll
        for (int r = 0; r < RPB; r++) acc[r] = fmaf(attn[r][j], ev, acc[r]);
    }
    if (h == 1) {
#pragma unroll
        for (int r = 0; r < RPB; r++) partial[r][col] = acc[r];
    }
    __syncthreads();
    if (h == 0) {
#pragma unroll
        for (int r = 0; r < RPB; r++) {
            int i = i0 + r;
            out[(size_t)i * (2 * E) + col] = embs[i * E + col];
            out[(size_t)i * (2 * E) + E + col] = (acc[r] + partial[r][col]) * inv[r];
        }
    }
}

// ---------------- launch ----------------
extern "C" void kernel_launch(void* const* d_in, const int* in_sizes, int n_in,
                              void* d_out, int out_size) {
    const float* embs = (const float*)d_in[0];
    const int*   adj  = (const int*)d_in[1];
    const float* pde  = (const float*)d_in[2];
    const float* W    = (const float*)d_in[3];
    const float* pcW  = (const float*)d_in[4];
    const float* pcb  = (const float*)d_in[5];
    const float* aW   = (const float*)d_in[6];
    const float* ab   = (const float*)d_in[7];
    float* out = (float*)d_out;

    cudaFuncSetAttribute(k_big, cudaFuncAttributeMaxDynamicSharedMemorySize,
                         (int)SMEM_DYN);

    k_pre<<<N, E>>>(embs, W, pcW, pcb, aW);                       // launch 0
    k_wa2<<<1, E>>>(W, aW);                                       // launch 1
    k_bh<<<E, E>>>(pcW);                                          // launch 2
    k_big<<<dim3(N / BMJ, N / I_PER_CTA), 256, SMEM_DYN>>>(pde, adj, ab);  // launch 3
    k_out<<<N / RPB, 256>>>(embs, out);                           // launch 4
}